// round 8
// baseline (speedup 1.0000x reference)
#include <cuda_runtime.h>

typedef unsigned long long ull;

#define BATCH 16
#define HH 128
#define WW 128
#define C4 32            // 128 channels as 32 float4 lanes
#define JCOLS 8          // output columns per thread
#define ROWSTEP (WW * C4)   // one image row, in float4 elements

// ---- packed fp32x2 primitives (sm_103a) ----
__device__ __forceinline__ ull mulp(ull a, ull b) {
    ull r; asm("mul.rn.f32x2 %0, %1, %2;" : "=l"(r) : "l"(a), "l"(b)); return r;
}
__device__ __forceinline__ ull addp(ull a, ull b) {
    ull r; asm("add.rn.f32x2 %0, %1, %2;" : "=l"(r) : "l"(a), "l"(b)); return r;
}
__device__ __forceinline__ ull fmap(ull a, ull b, ull c) {
    ull r; asm("fma.rn.f32x2 %0, %1, %2, %3;" : "=l"(r) : "l"(a), "l"(b), "l"(c)); return r;
}
__device__ __forceinline__ ull pack2f(float x) {
    ull r; asm("mov.b64 %0, {%1, %1};" : "=l"(r) : "f"(x)); return r;
}
__device__ __forceinline__ ull absp(ull u) {
    return u & 0x7FFFFFFF7FFFFFFFULL;   // clear both sign bits (one LOP3)
}

struct V4 { ull a, b; };   // 4 floats = one 16B vector

// 0.25*x + 0.75*y  (packed, both halves)
__device__ __forceinline__ V4 mix4(const V4& x, const V4& y, ull w25, ull w75) {
    V4 r;
    r.a = fmap(x.a, w25, mulp(y.a, w75));
    r.b = fmap(x.b, w25, mulp(y.b, w75));
    return r;
}

__device__ __forceinline__ V4 ldv(const ulonglong2* __restrict__ p) {
    ulonglong2 v = *p;                   // LDG.E.128
    V4 r; r.a = v.x; r.b = v.y;
    return r;
}
// streaming 16B store
__device__ __forceinline__ void stv(ulonglong2* p, ull lo, ull hi) {
    asm volatile("st.global.cs.v2.u64 [%0], {%1, %2};"
                 :: "l"(p), "l"(lo), "l"(hi) : "memory");
}

// 0.25 * sum lrelu(u_k) == ca*sum(u) + cb*sum(|u|), per ull half
__device__ __forceinline__ ull blend1(ull u00, ull u01, ull u10, ull u11, ull ca, ull cb) {
    ull sl = addp(addp(u00, u01), addp(u10, u11));
    ull sa = addp(addp(absp(u00), absp(u01)), addp(absp(u10), absp(u11)));
    return fmap(sl, ca, mulp(sa, cb));
}

// block = (32 float4-lanes, 4 col-groups) = 128 threads
// each thread: one float4 lane, 2 output rows x JCOLS=8 output columns.
// grid = (W/(8*4)=4, H/2=64, B=16)
__global__ __launch_bounds__(128)
void act_filter_kernel(const ulonglong2* __restrict__ X, ulonglong2* __restrict__ O) {
    const int lane = threadIdx.x;                    // 0..31
    const int jg = blockIdx.x * 4 + threadIdx.y;     // 0..15
    const int j0 = jg * JCOLS;
    const int i0 = blockIdx.y * 2;                   // output rows i0, i0+1
    const int b  = blockIdx.z;

    const ull w25 = pack2f(0.25f);
    const ull w75 = pack2f(0.75f);
    const ull ca  = pack2f(0.12625f);   // 0.505*0.25  (lrelu = 0.505u + 0.495|u|)
    const ull cb  = pack2f(0.12375f);   // 0.495*0.25

    const int row0 = (b * HH + i0) * WW;
    const int dm  = (i0 > 0)      ? -ROWSTEP     : 0;        // row i0-1 (clamped)
    const int dp2 = (i0 + 2 < HH) ?  2 * ROWSTEP : ROWSTEP;  // row i0+2 (clamped)

    const ulonglong2* __restrict__ p0 = X + (size_t)row0 * C4 + lane;   // + col*C4
    ulonglong2* __restrict__ po = O + ((size_t)row0 + j0) * C4 + lane;  // + jj*C4

    // vertical mixes, rotating 3-column window; A = out row i0, B = out row i0+1
    V4 vpA[3], vqA[3], vpB[3], vqB[3];

#pragma unroll
    for (int t = 0; t < JCOLS + 2; t++) {
        int col = j0 - 1 + t;
        if (t == 0)          col = (col > 0) ? col : 0;
        if (t == JCOLS + 1)  col = (col < WW) ? col : WW - 1;
        const int off = col * C4;

        // 4 independent 16B loads (rows i0-1 .. i0+2)
        V4 xm = ldv(p0 + off + dm);
        V4 x0 = ldv(p0 + off);
        V4 x1 = ldv(p0 + off + ROWSTEP);
        V4 x2 = ldv(p0 + off + dp2);

        const int s = t % 3;
        vpA[s] = mix4(xm, x0, w25, w75);   // 0.25 x[i0-1] + 0.75 x[i0]
        vqA[s] = mix4(x1, x0, w25, w75);   // 0.75 x[i0]   + 0.25 x[i0+1]
        vpB[s] = mix4(x0, x1, w25, w75);   // 0.25 x[i0]   + 0.75 x[i0+1]
        vqB[s] = mix4(x2, x1, w25, w75);   // 0.75 x[i0+1] + 0.25 x[i0+2]

        if (t >= 2) {
            const int sA = (t - 2) % 3, sB = (t - 1) % 3;
            // ---- output row i0 ----
            {
                V4 u00 = mix4(vpA[sA], vpA[sB], w25, w75);
                V4 u01 = mix4(vpA[s],  vpA[sB], w25, w75);
                V4 u10 = mix4(vqA[sA], vqA[sB], w25, w75);
                V4 u11 = mix4(vqA[s],  vqA[sB], w25, w75);
                ull lo = blend1(u00.a, u01.a, u10.a, u11.a, ca, cb);
                ull hi = blend1(u00.b, u01.b, u10.b, u11.b, ca, cb);
                stv(po + (t - 2) * C4, lo, hi);
            }
            // ---- output row i0+1 ----
            {
                V4 u00 = mix4(vpB[sA], vpB[sB], w25, w75);
                V4 u01 = mix4(vpB[s],  vpB[sB], w25, w75);
                V4 u10 = mix4(vqB[sA], vqB[sB], w25, w75);
                V4 u11 = mix4(vqB[s],  vqB[sB], w25, w75);
                ull lo = blend1(u00.a, u01.a, u10.a, u11.a, ca, cb);
                ull hi = blend1(u00.b, u01.b, u10.b, u11.b, ca, cb);
                stv(po + ROWSTEP + (t - 2) * C4, lo, hi);
            }
        }
    }
}

extern "C" void kernel_launch(void* const* d_in, const int* in_sizes, int n_in,
                              void* d_out, int out_size) {
    const ulonglong2* X = (const ulonglong2*)d_in[0];
    ulonglong2* O = (ulonglong2*)d_out;
    dim3 block(C4, 4, 1);
    dim3 grid(WW / (JCOLS * 4), HH / 2, BATCH);  // 4, 64, 16
    act_filter_kernel<<<grid, block>>>(X, O);
}

// round 9
// speedup vs baseline: 1.0612x; 1.0612x over previous
#include <cuda_runtime.h>

typedef unsigned long long ull;

#define BATCH 16
#define HH 128
#define WW 128
#define LANES 64         // 128 channels as 64 packed-f32x2 lanes
#define JCOLS 8          // output columns per thread
#define ROWSTEP (WW * LANES)

// ---- packed fp32x2 primitives (sm_103a) ----
__device__ __forceinline__ ull mulp(ull a, ull b) {
    ull r; asm("mul.rn.f32x2 %0, %1, %2;" : "=l"(r) : "l"(a), "l"(b)); return r;
}
__device__ __forceinline__ ull addp(ull a, ull b) {
    ull r; asm("add.rn.f32x2 %0, %1, %2;" : "=l"(r) : "l"(a), "l"(b)); return r;
}
__device__ __forceinline__ ull fmap(ull a, ull b, ull c) {
    ull r; asm("fma.rn.f32x2 %0, %1, %2, %3;" : "=l"(r) : "l"(a), "l"(b), "l"(c)); return r;
}
__device__ __forceinline__ ull pack2f(float x) {
    ull r; asm("mov.b64 %0, {%1, %1};" : "=l"(r) : "f"(x)); return r;
}
__device__ __forceinline__ ull absp(ull u) {
    return u & 0x7FFFFFFF7FFFFFFFULL;   // clear both sign bits (one LOP3)
}
// 0.25*x + 0.75*y
__device__ __forceinline__ ull mixp(ull x, ull y, ull w25, ull w75) {
    return fmap(x, w25, mulp(y, w75));
}
// streaming (evict-first) 8B store
__device__ __forceinline__ void stcs8(ull* p, ull v) {
    asm volatile("st.global.cs.b64 [%0], %1;" :: "l"(p), "l"(v) : "memory");
}

// clamped source-column index for window position t (t in 0..JCOLS+1)
__device__ __forceinline__ int src_col(int j0, int t) {
    int col = j0 - 1 + t;
    if (t == 0)          col = (col > 0) ? col : 0;
    if (t == JCOLS + 1)  col = (col < WW) ? col : WW - 1;
    return col;
}

// block = (64 lanes, 2 col-groups) = 128 threads
// each thread: one 2-channel lane, 2 output rows x JCOLS=8 output columns,
// with explicit next-column prefetch (software pipeline depth 1).
// grid = (8, H/2=64, B=16)
__global__ __launch_bounds__(128, 8)
void act_filter_kernel(const ull* __restrict__ X, ull* __restrict__ O) {
    const int lane = threadIdx.x;                    // 0..63
    const int jg = blockIdx.x * 2 + threadIdx.y;     // 0..15
    const int j0 = jg * JCOLS;
    const int i0 = blockIdx.y * 2;                   // output rows i0, i0+1
    const int b  = blockIdx.z;

    const ull w25 = pack2f(0.25f);
    const ull w75 = pack2f(0.75f);
    const ull ca  = pack2f(0.12625f);   // 0.505*0.25  (lrelu = 0.505u + 0.495|u|)
    const ull cb  = pack2f(0.12375f);   // 0.495*0.25

    const int row0 = (b * HH + i0) * WW;
    const int dm  = (i0 > 0)      ? -ROWSTEP     : 0;        // row i0-1 (clamped)
    const int dp2 = (i0 + 2 < HH) ?  2 * ROWSTEP : ROWSTEP;  // row i0+2 (clamped)

    const ull* __restrict__ p0 = X + (size_t)row0 * LANES + lane;       // + col*LANES
    ull* __restrict__ po = O + ((size_t)row0 + j0) * LANES + lane;      // + jj*LANES

    // vertical mixes, rotating 3-column window; A = out row i0, B = out row i0+1
    ull vpA[3], vqA[3], vpB[3], vqB[3];

    // ---- prologue: load column t=0 ----
    ull xm, x0, x1, x2;
    {
        const int off = src_col(j0, 0) * LANES;
        xm = p0[off + dm];
        x0 = p0[off];
        x1 = p0[off + ROWSTEP];
        x2 = p0[off + dp2];
    }

#pragma unroll
    for (int t = 0; t < JCOLS + 2; t++) {
        // ---- prefetch column t+1 before consuming column t ----
        ull nm = 0, n0 = 0, n1 = 0, n2 = 0;
        if (t < JCOLS + 1) {
            const int off = src_col(j0, t + 1) * LANES;
            nm = p0[off + dm];
            n0 = p0[off];
            n1 = p0[off + ROWSTEP];
            n2 = p0[off + dp2];
        }

        // ---- consume column t ----
        const int s = t % 3;
        vpA[s] = mixp(xm, x0, w25, w75);   // 0.25 x[i0-1] + 0.75 x[i0]
        vqA[s] = mixp(x1, x0, w25, w75);   // 0.75 x[i0]   + 0.25 x[i0+1]
        vpB[s] = mixp(x0, x1, w25, w75);   // 0.25 x[i0]   + 0.75 x[i0+1]
        vqB[s] = mixp(x2, x1, w25, w75);   // 0.75 x[i0+1] + 0.25 x[i0+2]

        if (t >= 2) {
            const int sA = (t - 2) % 3, sB = (t - 1) % 3;
            // ---- output row i0 ----
            {
                ull u00 = mixp(vpA[sA], vpA[sB], w25, w75);
                ull u01 = mixp(vpA[s],  vpA[sB], w25, w75);
                ull u10 = mixp(vqA[sA], vqA[sB], w25, w75);
                ull u11 = mixp(vqA[s],  vqA[sB], w25, w75);
                ull sl = addp(addp(u00, u01), addp(u10, u11));
                ull sa = addp(addp(absp(u00), absp(u01)), addp(absp(u10), absp(u11)));
                stcs8(po + (t - 2) * LANES, fmap(sl, ca, mulp(sa, cb)));
            }
            // ---- output row i0+1 ----
            {
                ull u00 = mixp(vpB[sA], vpB[sB], w25, w75);
                ull u01 = mixp(vpB[s],  vpB[sB], w25, w75);
                ull u10 = mixp(vqB[sA], vqB[sB], w25, w75);
                ull u11 = mixp(vqB[s],  vqB[sB], w25, w75);
                ull sl = addp(addp(u00, u01), addp(u10, u11));
                ull sa = addp(addp(absp(u00), absp(u01)), addp(absp(u10), absp(u11)));
                stcs8(po + ROWSTEP + (t - 2) * LANES, fmap(sl, ca, mulp(sa, cb)));
            }
        }

        // ---- rotate pipeline ----
        xm = nm; x0 = n0; x1 = n1; x2 = n2;
    }
}

extern "C" void kernel_launch(void* const* d_in, const int* in_sizes, int n_in,
                              void* d_out, int out_size) {
    const ull* X = (const ull*)d_in[0];
    ull* O = (ull*)d_out;
    dim3 block(LANES, 2, 1);
    dim3 grid(WW / (JCOLS * 2), HH / 2, BATCH);  // 8, 64, 16
    act_filter_kernel<<<grid, block>>>(X, O);
}

// round 11
// speedup vs baseline: 1.0889x; 1.0262x over previous
#include <cuda_runtime.h>
#include <cstdint>

typedef unsigned long long ull;

#define BATCH 16
#define HH 128
#define WW 128
#define LANES 64          // 128 channels = 64 ull lanes
#define TROWS 16          // output rows per block
#define TCOLS 16          // output cols per block
#define NCOLS 18          // staged cols per row segment (halo included)
#define RING 5            // ring depth (5*18*64*8 = 46080 B static smem)
#define SEG_ULL (NCOLS * LANES)          // 1152 ull per row segment
#define SEG_BYTES (SEG_ULL * 8)          // 9216
#define SEG_CHUNKS (SEG_BYTES / 16)      // 576 x 16B
#define THREADS 256

// ---- packed fp32x2 primitives (sm_103a) ----
__device__ __forceinline__ ull mulp(ull a, ull b) {
    ull r; asm("mul.rn.f32x2 %0, %1, %2;" : "=l"(r) : "l"(a), "l"(b)); return r;
}
__device__ __forceinline__ ull addp(ull a, ull b) {
    ull r; asm("add.rn.f32x2 %0, %1, %2;" : "=l"(r) : "l"(a), "l"(b)); return r;
}
__device__ __forceinline__ ull fmap(ull a, ull b, ull c) {
    ull r; asm("fma.rn.f32x2 %0, %1, %2, %3;" : "=l"(r) : "l"(a), "l"(b), "l"(c)); return r;
}
__device__ __forceinline__ ull pack2f(float x) {
    ull r; asm("mov.b64 %0, {%1, %1};" : "=l"(r) : "f"(x)); return r;
}
__device__ __forceinline__ ull absp(ull u) { return u & 0x7FFFFFFF7FFFFFFFULL; }
__device__ __forceinline__ ull mixp(ull x, ull y, ull w25, ull w75) {
    return fmap(x, w25, mulp(y, w75));       // 0.25x + 0.75y
}
__device__ __forceinline__ void stcs8(ull* p, ull v) {
    asm volatile("st.global.cs.b64 [%0], %1;" :: "l"(p), "l"(v) : "memory");
}

// ---- cp.async helpers ----
__device__ __forceinline__ void cp16(uint32_t saddr, const void* g) {
    asm volatile("cp.async.ca.shared.global [%0], [%1], 16;" :: "r"(saddr), "l"(g));
}
__device__ __forceinline__ void cp_commit() {
    asm volatile("cp.async.commit_group;" ::: "memory");
}
template <int N> __device__ __forceinline__ void cp_wait() {
    asm volatile("cp.async.wait_group %0;" :: "n"(N) : "memory");
}
__device__ __forceinline__ ull lds8(uint32_t a) {
    ull v; asm volatile("ld.shared.b64 %0, [%1];" : "=l"(v) : "r"(a)); return v;
}

// block = 256 threads: lane = tid&63 (ull channel), cg = tid>>6 (4 col groups of 4)
// tile: 16 output rows x 16 output cols x 128 ch; grid = (8, 8, 16) = 1024 blocks
__global__ __launch_bounds__(THREADS)
void act_filter_kernel(const ull* __restrict__ X, ull* __restrict__ O) {
    __shared__ ull ring[RING][SEG_ULL];

    const int tid  = threadIdx.x;
    const int lane = tid & (LANES - 1);
    const int cg   = tid >> 6;                  // 0..3
    const int j0   = blockIdx.x * TCOLS;
    const int i0   = blockIdx.y * TROWS;
    const int b    = blockIdx.z;

    // staged column range start (clamped so [cstart, cstart+17] subset of [0,127])
    const int cstart = (j0 == 0) ? 0 : ((j0 == WW - TCOLS) ? (WW - NCOLS) : j0 - 1);

    const ull w25 = pack2f(0.25f);
    const ull w75 = pack2f(0.75f);
    const ull ca  = pack2f(0.12625f);   // 0.505*0.25  (lrelu = 0.505u + 0.495|u|)
    const ull cb  = pack2f(0.12375f);   // 0.495*0.25

    const uint32_t sring = (uint32_t)__cvta_generic_to_shared(&ring[0][0]);

    // producer: stage input row k (k indexes rows i0-1 .. i0+16) into slot k%RING
    auto issue_row = [&](int k) {
        int rin = i0 - 1 + k;
        rin = (rin < 0) ? 0 : ((rin > HH - 1) ? HH - 1 : rin);
        const char* gsrc = (const char*)(X + ((size_t)((b * HH + rin) * WW + cstart)) * LANES);
        const uint32_t sbase = sring + (k % RING) * SEG_BYTES;
#pragma unroll
        for (int c = tid; c < SEG_CHUNKS; c += THREADS)
            cp16(sbase + c * 16, gsrc + (size_t)c * 16);
        cp_commit();
    };

    // prologue: stage rows k = 0..3
    issue_row(0); issue_row(1); issue_row(2); issue_row(3);

    // local clamped source columns for this thread's 6-col window
    const int j0c = j0 + cg * 4;
    int wc[6];
#pragma unroll
    for (int t = 0; t < 6; t++) {
        int c = j0c - 1 + t;
        c = (c < 0) ? 0 : ((c > WW - 1) ? WW - 1 : c);
        wc[t] = (c - cstart) * LANES + lane;   // ull index within a segment
    }

    ull* __restrict__ po = O + ((size_t)((b * HH + i0) * WW + j0c)) * LANES + lane;

#pragma unroll
    for (int r = 0; r < TROWS; r++) {
        // rows k=r..r+2 must be resident; groups issued so far: 4 + r
        if (r < TROWS - 1) cp_wait<1>(); else cp_wait<0>();
        __syncthreads();                       // staged rows visible; slot k=r-1 retired
        if (r + 4 <= TROWS + 1) issue_row(r + 4);   // stage ahead into freed slot

        const uint32_t sm = sring + ((r    ) % RING) * SEG_BYTES;  // row i-1
        const uint32_t s0 = sring + ((r + 1) % RING) * SEG_BYTES;  // row i
        const uint32_t sp = sring + ((r + 2) % RING) * SEG_BYTES;  // row i+1

        ull vp[3], vq[3];
#pragma unroll
        for (int t = 0; t < 6; t++) {
            const uint32_t off = wc[t] * 8;
            ull xm = lds8(sm + off);
            ull x0 = lds8(s0 + off);
            ull xp = lds8(sp + off);
            const int s = t % 3;
            vp[s] = mixp(xm, x0, w25, w75);
            vq[s] = mixp(xp, x0, w25, w75);
            if (t >= 2) {
                const int sA = (t - 2) % 3, sB = (t - 1) % 3;
                ull u00 = mixp(vp[sA], vp[sB], w25, w75);
                ull u01 = mixp(vp[s],  vp[sB], w25, w75);
                ull u10 = mixp(vq[sA], vq[sB], w25, w75);
                ull u11 = mixp(vq[s],  vq[sB], w25, w75);
                ull sl = addp(addp(u00, u01), addp(u10, u11));
                ull sa = addp(addp(absp(u00), absp(u01)), addp(absp(u10), absp(u11)));
                stcs8(po + (size_t)r * WW * LANES + (t - 2) * LANES,
                      fmap(sl, ca, mulp(sa, cb)));
            }
        }
    }
}

extern "C" void kernel_launch(void* const* d_in, const int* in_sizes, int n_in,
                              void* d_out, int out_size) {
    const ull* X = (const ull*)d_in[0];
    ull* O = (ull*)d_out;
    dim3 block(THREADS, 1, 1);
    dim3 grid(WW / TCOLS, HH / TROWS, BATCH);   // 8, 8, 16
    act_filter_kernel<<<grid, block>>>(X, O);
}